// round 9
// baseline (speedup 1.0000x reference)
#include <cuda_runtime.h>
#include <cuda_bf16.h>

// Problem constants
#define B_   8192
#define M_   50000
#define NU_  16
#define F_   128
#define E_   65536

#define SCATTER_BLOCKS ((E_ * 32) / 1024)  // 2048: each thread handles 2 chunks
#define HALF_ (E_ * 16)                    // 1048576: second-chunk offset
#define DUP_BLOCKS (B_ / 8)                // 1024: 8 warps/block, 1 b per warp
#define KA_GRID (M_ + DUP_BLOCKS)          // 51024

// Scratch (device globals — no allocation allowed)
__device__ float4 g_h1agg4[B_ * (F_ / 4)];   // h1_agg  [B,F]
__device__ float4 g_h2agg4[B_ * (F_ / 4)];   // h2_agg  [B,F]
__device__ int    g_winner[M_];              // winning b per V_n row (max b), -1 if untouched

// ---------------------------------------------------------------------------
// K1: init scratch (every replay — deterministic)
// ---------------------------------------------------------------------------
__global__ void init_kernel() {
    int t = blockIdx.x * blockDim.x + threadIdx.x;
    const int NV = B_ * (F_ / 4);  // 262144
    if (t < NV) {
        g_h1agg4[t] = make_float4(0.f, 0.f, 0.f, 0.f);
        g_h2agg4[t] = make_float4(0.f, 0.f, 0.f, 0.f);
    }
    if (t < M_) g_winner[t] = -1;
}

// ---------------------------------------------------------------------------
// K2: segment sums via float4 atomics (2 chunks/thread, MLP=4) + winner max
//   chunk t0 covers e0 = t0>>5; chunk t0+HALF_ covers e1 = e0 + E/2.
//   All 4 streaming loads issue before any RED — fills the memory pipe.
// ---------------------------------------------------------------------------
__global__ __launch_bounds__(512)
void scatter_kernel(const float4* __restrict__ h1_4,
                    const int*    __restrict__ h1_idx,
                    const float4* __restrict__ h2_4,
                    const int*    __restrict__ h2_idx,
                    const int*    __restrict__ v_idx) {
    int t0 = blockIdx.x * 512 + threadIdx.x;     // in [0, E*16)
    int t1 = t0 + HALF_;
    int e0 = t0 >> 5, e1 = t1 >> 5;
    int c  = t0 & 31;

    // 4 independent streaming loads (MLP=4)
    float4 a0 = __ldcs(h1_4 + t0);
    float4 b0 = __ldcs(h2_4 + t0);
    float4 a1 = __ldcs(h1_4 + t1);
    float4 b1 = __ldcs(h2_4 + t1);

    int ia0 = __ldg(h1_idx + e0) * 32 + c;
    int ib0 = __ldg(h2_idx + e0) * 32 + c;
    int ia1 = __ldg(h1_idx + e1) * 32 + c;
    int ib1 = __ldg(h2_idx + e1) * 32 + c;

    atomicAdd(&g_h1agg4[ia0], a0);
    atomicAdd(&g_h2agg4[ib0], b0);
    atomicAdd(&g_h1agg4[ia1], a1);
    atomicAdd(&g_h2agg4[ib1], b1);

    if (t0 < B_) atomicMax(&g_winner[__ldg(v_idx + t0)], t0);
}

// ---------------------------------------------------------------------------
// KA: one kernel, two block flavors.
//   bid <  M_ : per-row copy (256 thr, 2 float4 each, MLP=2);
//               winner rows run the full in-register pipeline:
//               dots -> gram matvec -> energy -> tanh -> write updated row.
//   bid >= M_ : dup-energy blocks — 8 warps, warp w handles b = (bid-M_)*8+w;
//               exits unless b gathers a row it did NOT win (~565 active).
// ---------------------------------------------------------------------------
__global__ __launch_bounds__(256)
void fused_kernel(const float*  __restrict__ Vn,
                  const float4* __restrict__ mo4,
                  const float*  __restrict__ gram,
                  const int*    __restrict__ v_idx,
                  float*        __restrict__ energy_out,
                  float*        __restrict__ vout) {
    int bid = blockIdx.x;

    if (bid >= M_) {
        // ---------------- dup-energy tail blocks ----------------
        int lane = threadIdx.x & 31;
        int b = (bid - M_) * 8 + (threadIdx.x >> 5);
        int row = __ldg(v_idx + b);
        if (g_winner[row] == b) return;      // winner's energy written below

        int i = b * 32 + lane;
        float4 m  = __ldg(mo4 + i);
        float4 a1 = g_h1agg4[i];
        float4 a2 = g_h2agg4[i];
        float4 g  = make_float4(m.x + a1.x + a2.x, m.y + a1.y + a2.y,
                                m.z + a1.z + a2.z, m.w + a1.w + a2.w);

        const float4* vrow = (const float4*)(Vn + (size_t)row * (NU_ * F_));
        const float*  gr   = gram + (size_t)b * (NU_ * NU_);
        float d = 0.f, l = 0.f;              // lane u (<16): denom_u, le_u
        #pragma unroll
        for (int u = 0; u < 16; u++) {
            float4 v = __ldg(vrow + u * 32 + lane);
            float o1 = v.x * m.x + v.y * m.y + v.z * m.z + v.w * m.w;
            float l1 = v.x * g.x + v.y * g.y + v.z * g.z + v.w * g.w;
            #pragma unroll
            for (int o = 16; o; o >>= 1) {
                o1 += __shfl_xor_sync(0xFFFFFFFF, o1, o);
                l1 += __shfl_xor_sync(0xFFFFFFFF, l1, o);
            }
            if (lane < 16) d += gr[lane * NU_ + u] * o1;
            if (lane == u) l = l1;
        }
        float d2 = d * d;
        float ns = (lane < 16) ? l * d2 : 0.f;
        float ds = (lane < 16) ? d2 : 0.f;
        #pragma unroll
        for (int o = 16; o; o >>= 1) {
            ns += __shfl_xor_sync(0xFFFFFFFF, ns, o);
            ds += __shfl_xor_sync(0xFFFFFFFF, ds, o);
        }
        if (lane == 0) energy_out[b] = ns / ds;
        return;
    }

    // ---------------- copy / winner blocks ----------------
    int row = bid;
    int t   = threadIdx.x;
    int win = g_winner[row];

    const float4* src = (const float4*)(Vn   + (size_t)row * (NU_ * F_));
    float4*       dst = (float4*)      (vout + (size_t)row * (NU_ * F_));
    float4 v1 = __ldcs(src + t);
    float4 v2 = __ldcs(src + t + 256);

    if (win < 0) {
        __stcs(dst + t,       v1);
        __stcs(dst + t + 256, v2);
        return;
    }

    // winner path: b = win; warp w handles u = w and u = w+8
    int w = t >> 5, c = t & 31;
    int i = win * 32 + c;
    float4 m  = __ldg(mo4 + i);
    float4 a1 = g_h1agg4[i];
    float4 a2 = g_h2agg4[i];
    float4 f  = make_float4(m.x + a1.x, m.y + a1.y, m.z + a1.z, m.w + a1.w); // feats
    float4 g  = make_float4(f.x + a2.x, f.y + a2.y, f.z + a2.z, f.w + a2.w); // feats+h2

    float ov1 = v1.x * m.x + v1.y * m.y + v1.z * m.z + v1.w * m.w;
    float le1 = v1.x * g.x + v1.y * g.y + v1.z * g.z + v1.w * g.w;
    float ov2 = v2.x * m.x + v2.y * m.y + v2.z * m.z + v2.w * m.w;
    float le2 = v2.x * g.x + v2.y * g.y + v2.z * g.z + v2.w * g.w;
    #pragma unroll
    for (int o = 16; o; o >>= 1) {
        ov1 += __shfl_xor_sync(0xFFFFFFFF, ov1, o);
        le1 += __shfl_xor_sync(0xFFFFFFFF, le1, o);
        ov2 += __shfl_xor_sync(0xFFFFFFFF, ov2, o);
        le2 += __shfl_xor_sync(0xFFFFFFFF, le2, o);
    }

    __shared__ float ov_s[16], le_s[16], dn_s[16];
    if (c == 0) {
        ov_s[w]     = ov1;  le_s[w]     = le1;
        ov_s[w + 8] = ov2;  le_s[w + 8] = le2;
    }
    __syncthreads();

    // warp 0: denom = gram[win] @ ov, p-weights, energy[win]
    if (w == 0) {
        float d = 0.f, l = 0.f;
        if (c < 16) {
            const float* gr = gram + (size_t)win * (NU_ * NU_) + c * NU_;
            #pragma unroll
            for (int k = 0; k < 16; k++) d += gr[k] * ov_s[k];
            l = le_s[c];
        }
        float d2 = d * d;
        float ns = l * d2;   // lanes >=16 contribute 0
        float ds = d2;
        #pragma unroll
        for (int o = 16; o; o >>= 1) {
            ns += __shfl_xor_sync(0xFFFFFFFF, ns, o);
            ds += __shfl_xor_sync(0xFFFFFFFF, ds, o);
        }
        if (c < 16) dn_s[c] = d;
        if (c == 0) energy_out[win] = ns / ds;
    }
    __syncthreads();

    // top_states = tanh(V + denom[u]*feats) — row still in registers
    float dn1 = dn_s[w], dn2 = dn_s[w + 8];
    float4 t1, t2;
    t1.x = tanhf(v1.x + dn1 * f.x);  t1.y = tanhf(v1.y + dn1 * f.y);
    t1.z = tanhf(v1.z + dn1 * f.z);  t1.w = tanhf(v1.w + dn1 * f.w);
    t2.x = tanhf(v2.x + dn2 * f.x);  t2.y = tanhf(v2.y + dn2 * f.y);
    t2.z = tanhf(v2.z + dn2 * f.z);  t2.w = tanhf(v2.w + dn2 * f.w);
    __stcs(dst + t,       t1);
    __stcs(dst + t + 256, t2);
}

// ---------------------------------------------------------------------------
extern "C" void kernel_launch(void* const* d_in, const int* in_sizes, int n_in,
                              void* d_out, int out_size) {
    const float* mo    = (const float*)d_in[0];
    const float* Vn    = (const float*)d_in[1];
    const int*   vidx  = (const int*)  d_in[2];
    const float* h1    = (const float*)d_in[3];
    const int*   h1i   = (const int*)  d_in[4];
    const float* h2    = (const float*)d_in[5];
    const int*   h2i   = (const int*)  d_in[6];
    const float* gram  = (const float*)d_in[7];

    float* energy = (float*)d_out;        // [B]
    float* vout   = energy + B_;          // [M, NU, F]

    {   // K1: zero aggregates, winner=-1
        int n = B_ * (F_ / 4);            // 262144 (>= M_)
        init_kernel<<<(n + 511) / 512, 512>>>();
    }
    // K2: segment sums (2 chunks/thread) + winner resolution
    scatter_kernel<<<SCATTER_BLOCKS, 512>>>(
        (const float4*)h1, h1i, (const float4*)h2, h2i, vidx);

    // KA: copy + winner pipeline + dup-energy tail (single pass over V_n)
    fused_kernel<<<KA_GRID, 256>>>(Vn, (const float4*)mo, gram, vidx, energy, vout);
}